// round 4
// baseline (speedup 1.0000x reference)
#include <cuda_runtime.h>
#include <cstdint>

// LJ constants (sigma = 1, epsilon = 1, cutoff = 5)
// SHIFT = 4*((1/5)^12 - (1/5)^6)
static __device__ __constant__ float c_shift = 4.0f * (float)(4.096e-09 - 6.4e-05);

__device__ __forceinline__ float lj_half_energy(float x, float y, float z) {
    float r2 = fmaf(x, x, fmaf(y, y, z * z));
    float inv = __fdividef(1.0f, r2);   // (sigma/r)^2, sigma = 1
    float sr6 = inv * inv * inv;        // (sigma/r)^6
    float e = fmaf(4.0f, fmaf(sr6, sr6, -sr6), -c_shift);
    return 0.5f * e;
}

// Persistent grid-stride kernel: 4 edges per thread per iteration.
// Exactly one wave of CTAs (gridDim chosen by host = SMs * 8) -> no wave
// transitions, minimal tail imbalance; the loop keeps the per-SM LSU
// continuously fed with atomic wavefronts (the binding resource).
__global__ void __launch_bounds__(256, 8) lj_persist_kernel(
    const float4* __restrict__ d4,
    const void* __restrict__ fa,
    const void* __restrict__ sa,
    float* __restrict__ out,
    int n_quads)
{
    __shared__ int s_idx64;
    if (threadIdx.x == 0) {
        // int64-LE with values < 2^31 -> odd 32-bit words all zero.
        // int32 indices in [0, 100000): odd words are real indices; the
        // all-zero false-positive probability is ~(1e-5)^8.
        const unsigned int* p = (const unsigned int*)fa;
        unsigned int acc = 0;
#pragma unroll
        for (int k = 0; k < 8; k++) acc |= p[2 * k + 1];
        s_idx64 = (acc == 0) ? 1 : 0;
    }
    __syncthreads();
    const int idx64 = s_idx64;

    const int stride = gridDim.x * blockDim.x;
    for (int i = blockIdx.x * blockDim.x + threadIdx.x; i < n_quads; i += stride) {
        // 4 edges = 12 floats = 3 x float4, fully coalesced.
        float4 a = d4[3 * (size_t)i + 0];
        float4 b = d4[3 * (size_t)i + 1];
        float4 c = d4[3 * (size_t)i + 2];

        float h0 = lj_half_energy(a.x, a.y, a.z);
        float h1 = lj_half_energy(a.w, b.x, b.y);
        float h2 = lj_half_energy(b.z, b.w, c.x);
        float h3 = lj_half_energy(c.y, c.z, c.w);

        if (!idx64) {
            int4 f = ((const int4*)fa)[i];
            int4 s = ((const int4*)sa)[i];
            atomicAdd(out + f.x, h0); atomicAdd(out + s.x, h0);
            atomicAdd(out + f.y, h1); atomicAdd(out + s.y, h1);
            atomicAdd(out + f.z, h2); atomicAdd(out + s.z, h2);
            atomicAdd(out + f.w, h3); atomicAdd(out + s.w, h3);
        } else {
            longlong2 f01 = ((const longlong2*)fa)[2 * (size_t)i + 0];
            longlong2 f23 = ((const longlong2*)fa)[2 * (size_t)i + 1];
            longlong2 s01 = ((const longlong2*)sa)[2 * (size_t)i + 0];
            longlong2 s23 = ((const longlong2*)sa)[2 * (size_t)i + 1];
            atomicAdd(out + f01.x, h0); atomicAdd(out + s01.x, h0);
            atomicAdd(out + f01.y, h1); atomicAdd(out + s01.y, h1);
            atomicAdd(out + f23.x, h2); atomicAdd(out + s23.x, h2);
            atomicAdd(out + f23.y, h3); atomicAdd(out + s23.y, h3);
        }
    }
}

// Scalar tail for n_edges not divisible by 4 (not expected for 6.4M, but safe).
__global__ void lj_tail_kernel(
    const float* __restrict__ dist,
    const void* __restrict__ fa,
    const void* __restrict__ sa,
    float* __restrict__ out,
    int start, int n_edges)
{
    __shared__ int s_idx64;
    if (threadIdx.x == 0) {
        const unsigned int* p = (const unsigned int*)fa;
        unsigned int acc = 0;
#pragma unroll
        for (int k = 0; k < 8; k++) acc |= p[2 * k + 1];
        s_idx64 = (acc == 0) ? 1 : 0;
    }
    __syncthreads();

    int e = start + blockIdx.x * blockDim.x + threadIdx.x;
    if (e >= n_edges) return;
    float x = dist[3 * (size_t)e + 0];
    float y = dist[3 * (size_t)e + 1];
    float z = dist[3 * (size_t)e + 2];
    float h = lj_half_energy(x, y, z);
    long long i0, i1;
    if (s_idx64) {
        i0 = ((const long long*)fa)[e];
        i1 = ((const long long*)sa)[e];
    } else {
        i0 = ((const int*)fa)[e];
        i1 = ((const int*)sa)[e];
    }
    atomicAdd(out + i0, h);
    atomicAdd(out + i1, h);
}

extern "C" void kernel_launch(void* const* d_in, const int* in_sizes, int n_in,
                              void* d_out, int out_size)
{
    const float* dist = (const float*)d_in[0];
    const void*  fa   = d_in[1];
    const void*  sa   = d_in[2];
    float* out = (float*)d_out;

    int n_edges = in_sizes[1];  // element count of first_atom

    // Zero per-atom accumulators (d_out is poisoned before timing).
    cudaMemsetAsync(d_out, 0, (size_t)out_size * sizeof(float));

    int quads = n_edges / 4;
    if (quads > 0) {
        int sm_count = 148;
        cudaDeviceGetAttribute(&sm_count, cudaDevAttrMultiProcessorCount, 0);
        int blocks = sm_count * 8;                  // exactly one resident wave
        int max_blocks = (quads + 255) / 256;
        if (blocks > max_blocks) blocks = max_blocks;
        lj_persist_kernel<<<blocks, 256>>>((const float4*)dist, fa, sa, out, quads);
    }
    int rem_start = quads * 4;
    if (rem_start < n_edges) {
        int rem = n_edges - rem_start;
        lj_tail_kernel<<<(rem + 255) / 256, 256>>>(dist, fa, sa, out, rem_start, n_edges);
    }
}

// round 5
// speedup vs baseline: 1.0834x; 1.0834x over previous
#include <cuda_runtime.h>
#include <cstdint>

// LJ constants (sigma = 1, epsilon = 1, cutoff = 5)
// SHIFT = 4*((1/5)^12 - (1/5)^6)
static __device__ __constant__ float c_shift = 4.0f * (float)(4.096e-09 - 6.4e-05);

__device__ __forceinline__ float lj_half_energy(float x, float y, float z) {
    float r2 = fmaf(x, x, fmaf(y, y, z * z));
    float inv = __fdividef(1.0f, r2);   // (sigma/r)^2, sigma = 1
    float sr6 = inv * inv * inv;        // (sigma/r)^6
    float e = fmaf(4.0f, fmaf(sr6, sr6, -sr6), -c_shift);
    return 0.5f * e;
}

// One-shot kernel, 4 edges per thread, block = 128 (small CTAs -> short drain
// tail at the end of the launch; the scatter-atomic wavefront queue is the
// binding resource, so geometry only matters at the ramp edges).
__global__ void __launch_bounds__(128) lj4_kernel(
    const float4* __restrict__ d4,
    const void* __restrict__ fa,
    const void* __restrict__ sa,
    float* __restrict__ out,
    int n_quads)
{
    __shared__ int s_idx64;
    if (threadIdx.x == 0) {
        // int64-LE with values < 2^31 -> odd 32-bit words all zero.
        // int32 indices in [0, 100000): odd words are real indices; all-zero
        // false-positive probability ~(1e-5)^8 -> negligible.
        const unsigned int* p = (const unsigned int*)fa;
        unsigned int acc = 0;
#pragma unroll
        for (int k = 0; k < 8; k++) acc |= p[2 * k + 1];
        s_idx64 = (acc == 0) ? 1 : 0;
    }
    __syncthreads();

    int i = blockIdx.x * blockDim.x + threadIdx.x;
    if (i >= n_quads) return;

    // 4 edges = 12 floats = 3 x float4, fully coalesced.
    float4 a = d4[3 * (size_t)i + 0];
    float4 b = d4[3 * (size_t)i + 1];
    float4 c = d4[3 * (size_t)i + 2];

    float h0 = lj_half_energy(a.x, a.y, a.z);
    float h1 = lj_half_energy(a.w, b.x, b.y);
    float h2 = lj_half_energy(b.z, b.w, c.x);
    float h3 = lj_half_energy(c.y, c.z, c.w);

    if (!s_idx64) {
        int4 f = ((const int4*)fa)[i];
        int4 s = ((const int4*)sa)[i];
        atomicAdd(out + f.x, h0); atomicAdd(out + s.x, h0);
        atomicAdd(out + f.y, h1); atomicAdd(out + s.y, h1);
        atomicAdd(out + f.z, h2); atomicAdd(out + s.z, h2);
        atomicAdd(out + f.w, h3); atomicAdd(out + s.w, h3);
    } else {
        longlong2 f01 = ((const longlong2*)fa)[2 * (size_t)i + 0];
        longlong2 f23 = ((const longlong2*)fa)[2 * (size_t)i + 1];
        longlong2 s01 = ((const longlong2*)sa)[2 * (size_t)i + 0];
        longlong2 s23 = ((const longlong2*)sa)[2 * (size_t)i + 1];
        atomicAdd(out + f01.x, h0); atomicAdd(out + s01.x, h0);
        atomicAdd(out + f01.y, h1); atomicAdd(out + s01.y, h1);
        atomicAdd(out + f23.x, h2); atomicAdd(out + s23.x, h2);
        atomicAdd(out + f23.y, h3); atomicAdd(out + s23.y, h3);
    }
}

// Scalar tail for n_edges not divisible by 4 (not expected for 6.4M, but safe).
__global__ void lj_tail_kernel(
    const float* __restrict__ dist,
    const void* __restrict__ fa,
    const void* __restrict__ sa,
    float* __restrict__ out,
    int start, int n_edges)
{
    __shared__ int s_idx64;
    if (threadIdx.x == 0) {
        const unsigned int* p = (const unsigned int*)fa;
        unsigned int acc = 0;
#pragma unroll
        for (int k = 0; k < 8; k++) acc |= p[2 * k + 1];
        s_idx64 = (acc == 0) ? 1 : 0;
    }
    __syncthreads();

    int e = start + blockIdx.x * blockDim.x + threadIdx.x;
    if (e >= n_edges) return;
    float x = dist[3 * (size_t)e + 0];
    float y = dist[3 * (size_t)e + 1];
    float z = dist[3 * (size_t)e + 2];
    float h = lj_half_energy(x, y, z);
    long long i0, i1;
    if (s_idx64) {
        i0 = ((const long long*)fa)[e];
        i1 = ((const long long*)sa)[e];
    } else {
        i0 = ((const int*)fa)[e];
        i1 = ((const int*)sa)[e];
    }
    atomicAdd(out + i0, h);
    atomicAdd(out + i1, h);
}

extern "C" void kernel_launch(void* const* d_in, const int* in_sizes, int n_in,
                              void* d_out, int out_size)
{
    const float* dist = (const float*)d_in[0];
    const void*  fa   = d_in[1];
    const void*  sa   = d_in[2];
    float* out = (float*)d_out;

    int n_edges = in_sizes[1];  // element count of first_atom

    // Zero per-atom accumulators (d_out is poisoned before timing).
    cudaMemsetAsync(d_out, 0, (size_t)out_size * sizeof(float));

    int quads = n_edges / 4;
    if (quads > 0) {
        int threads = 128;
        int blocks = (quads + threads - 1) / threads;
        lj4_kernel<<<blocks, threads>>>((const float4*)dist, fa, sa, out, quads);
    }
    int rem_start = quads * 4;
    if (rem_start < n_edges) {
        int rem = n_edges - rem_start;
        lj_tail_kernel<<<(rem + 255) / 256, 256>>>(dist, fa, sa, out, rem_start, n_edges);
    }
}